// round 13
// baseline (speedup 1.0000x reference)
#include <cuda_runtime.h>
#include <cuda_bf16.h>
#include <math.h>
#include <cstdint>

#define D_FIX 256
#define C_MAX 50176
#define B_MAX 512
#define TS 272          // smem tile row stride in bytes (256 data + 16 pad)

// ---- device scratch (allocation-free: __device__ globals) ----
__device__ unsigned char g_tn8[(size_t)C_MAX * D_FIX];   // fp8 text (compact, x16)
__device__ unsigned char g_vn8[(size_t)B_MAX * D_FIX];   // fp8 visual (x16)
__device__ float g_denom[B_MAX];
__device__ float g_pos[B_MAX];
__device__ int   g_npos[B_MAX];

// ---------------------------------------------------------------------------
__device__ __forceinline__ unsigned smemu32(const void* p) {
    return (unsigned)__cvta_generic_to_shared(p);
}
#define CP_ASYNC16(dst, src) \
    asm volatile("cp.async.cg.shared.global [%0], [%1], 16;\n" :: "r"(dst), "l"(src))
#define CP_COMMIT()  asm volatile("cp.async.commit_group;\n")
#define CP_WAIT0()   asm volatile("cp.async.wait_group 0;\n" ::: "memory")

// pack 4 floats -> 4 e4m3 bytes (byte0 = a); cvt.e4m3x2 writes a b16 dest
__device__ __forceinline__ unsigned pack_e4m3x4(float a, float b, float c, float d) {
    unsigned short lo, hi;
    asm("cvt.rn.satfinite.e4m3x2.f32 %0, %1, %2;" : "=h"(lo) : "f"(b), "f"(a));
    asm("cvt.rn.satfinite.e4m3x2.f32 %0, %1, %2;" : "=h"(hi) : "f"(d), "f"(c));
    return ((unsigned)hi << 16) | (unsigned)lo;
}

__device__ __forceinline__ void mma_e4m3(float c[4], const unsigned a[4],
                                         unsigned b0, unsigned b1) {
    asm volatile(
        "mma.sync.aligned.m16n8k32.row.col.f32.e4m3.e4m3.f32 "
        "{%0,%1,%2,%3}, {%4,%5,%6,%7}, {%8,%9}, {%0,%1,%2,%3};\n"
        : "+f"(c[0]), "+f"(c[1]), "+f"(c[2]), "+f"(c[3])
        : "r"(a[0]), "r"(a[1]), "r"(a[2]), "r"(a[3]), "r"(b0), "r"(b1));
}

// ---------------------------------------------------------------------------
// pad-zero only (launched only when NL % 64 != 0)
__global__ void zero_pad_kernel(int padBytes, size_t padOff) {
    int i = blockIdx.x * blockDim.x + threadIdx.x;
    if (i < padBytes) g_tn8[padOff + i] = 0;
}

// warp-per-row normalize -> fp8 (x16). gather=1: row i reads x[ids[i]].
// gather==0 (visual) also zeroes the per-row stat accumulators.
__global__ void norm_fp8_kernel(const float* __restrict__ x,
                                const int* __restrict__ ids,
                                int rows, float eps, int gather, int isText) {
    int i = blockIdx.x * 8 + (threadIdx.x >> 5);
    if (i >= rows) return;
    int lane = threadIdx.x & 31;
    if (!gather && lane == 0) { g_denom[i] = 0.f; g_pos[i] = 0.f; g_npos[i] = 0; }
    int srcRow = gather ? ids[i] : i;
    const float4* xr = (const float4*)(x + (size_t)srcRow * D_FIX);
    float4 t0 = xr[lane], t1 = xr[lane + 32];
    float ss = t0.x * t0.x + t0.y * t0.y + t0.z * t0.z + t0.w * t0.w
             + t1.x * t1.x + t1.y * t1.y + t1.z * t1.z + t1.w * t1.w;
#pragma unroll
    for (int o = 16; o > 0; o >>= 1) ss += __shfl_xor_sync(0xffffffffu, ss, o);
    float inv = 16.0f / (eps + sqrtf(ss));
    unsigned w0 = pack_e4m3x4(t0.x * inv, t0.y * inv, t0.z * inv, t0.w * inv);
    unsigned w1 = pack_e4m3x4(t1.x * inv, t1.y * inv, t1.z * inv, t1.w * inv);
    unsigned* dst = (unsigned*)(isText ? g_tn8 : g_vn8) + (size_t)i * 64;
    dst[lane]      = w0;
    dst[lane + 32] = w1;
}

// ---------------------------------------------------------------------------
// fp8 GEMM tile 128(M)x64(N), warp tile 32x32, full K=256 resident,
// 4 CTAs/SM target, fused label gather (2 batches of 16) + loss epilogue.
__global__ __launch_bounds__(256, 4)
void gemm_loss8(const int* __restrict__ label, const int* __restrict__ ids,
                int B, int C, int NL) {
    extern __shared__ unsigned char dynraw[];
    __shared__ float sdn[128], sps[128];
    __shared__ int sns[128];

    const int tid = threadIdx.x;
    const int cbase = blockIdx.x * 64;       // compact column base
    const int rbase = blockIdx.y * 128;

    const unsigned aB = smemu32(dynraw);
    const unsigned bB = aB + 128u * TS;

    // async tile loads: A 128 rows (8 chunks/thread), B 64 rows (4 chunks/thread)
#pragma unroll
    for (int m = 0; m < 8; ++m) {
        int id = m * 256 + tid;
        int r = id >> 4, cb = id & 15;
        CP_ASYNC16(aB + (unsigned)(r * TS + cb * 16),
                   g_vn8 + (size_t)(rbase + r) * D_FIX + cb * 16);
    }
#pragma unroll
    for (int m = 0; m < 4; ++m) {
        int id = m * 256 + tid;
        int r = id >> 4, cb = id & 15;
        CP_ASYNC16(bB + (unsigned)(r * TS + cb * 16),
                   g_tn8 + (size_t)(cbase + r) * D_FIX + cb * 16);
    }
    CP_COMMIT();

    if (tid < 128) { sdn[tid] = 0.f; sps[tid] = 0.f; sns[tid] = 0; }

    const int lane = tid & 31, wid = tid >> 5;
    const int g = lane >> 2, tig = lane & 3;
    const int warp_m = wid & 3, warp_n = wid >> 2;   // 4 x 2
    const int grp = lane >> 3, rin = lane & 7;

    // ---- fused label gather: 8 cols x 4 rows, two MLP-16 batches ----
    int idv[8]; unsigned vbits = 0;
#pragma unroll
    for (int k = 0; k < 8; ++k) {
        int cl = warp_n * 32 + (k >> 1) * 8 + 2 * tig + (k & 1);
        int gc = cbase + cl;
        bool v = (gc < NL);
        if (v) vbits |= 1u << k;
        idv[k] = ids[v ? gc : (NL - 1)];
    }
    unsigned pmw = 0, nmw = 0;    // packed: row-group r occupies bits [8r, 8r+8)
#pragma unroll
    for (int half = 0; half < 2; ++half) {
        int labs[2][8];
#pragma unroll
        for (int rr = 0; rr < 2; ++rr) {
            int r = half * 2 + rr;
            int rl = warp_m * 32 + (r >> 1) * 16 + (r & 1) * 8 + g;
            const int* lrow = label + (size_t)(rbase + rl) * C;
#pragma unroll
            for (int k = 0; k < 8; ++k) labs[rr][k] = __ldg(&lrow[idv[k]]);
        }
#pragma unroll
        for (int rr = 0; rr < 2; ++rr) {
            int r = half * 2 + rr;
#pragma unroll
            for (int k = 0; k < 8; ++k) {
                if ((vbits >> k) & 1) {
                    if (labs[rr][k] != 0) pmw |= 1u << (8 * r + k);
                    else                  nmw |= 1u << (8 * r + k);
                }
            }
        }
    }

    float acc[2][4][4];
#pragma unroll
    for (int i = 0; i < 2; i++)
#pragma unroll
        for (int j = 0; j < 4; j++)
#pragma unroll
            for (int k = 0; k < 4; k++) acc[i][j][k] = 0.f;

    CP_WAIT0();
    __syncthreads();

    unsigned aBase[2], bBase[2];
#pragma unroll
    for (int mt = 0; mt < 2; ++mt) {
        int rowA = warp_m * 32 + mt * 16 + (grp & 1) * 8 + rin;
        aBase[mt] = aB + (unsigned)(rowA * TS + (grp >> 1) * 16);
    }
#pragma unroll
    for (int p = 0; p < 2; ++p) {
        int rowB = warp_n * 32 + p * 16 + ((grp & 2) ? 8 : 0) + rin;
        bBase[p] = bB + (unsigned)(rowB * TS + (grp & 1) * 16);
    }

#pragma unroll
    for (int ks = 0; ks < 8; ++ks) {          // K = 8 x 32 fp8
        const unsigned kof = ks * 32;
        unsigned a[2][4], b[2][4];
#pragma unroll
        for (int mt = 0; mt < 2; ++mt)
            asm volatile(
                "ldmatrix.sync.aligned.m8n8.x4.shared.b16 {%0,%1,%2,%3}, [%4];\n"
                : "=r"(a[mt][0]), "=r"(a[mt][1]), "=r"(a[mt][2]), "=r"(a[mt][3])
                : "r"(aBase[mt] + kof));
#pragma unroll
        for (int p = 0; p < 2; ++p)
            asm volatile(
                "ldmatrix.sync.aligned.m8n8.x4.shared.b16 {%0,%1,%2,%3}, [%4];\n"
                : "=r"(b[p][0]), "=r"(b[p][1]), "=r"(b[p][2]), "=r"(b[p][3])
                : "r"(bBase[p] + kof));
#pragma unroll
        for (int p = 0; p < 2; ++p) {
            mma_e4m3(acc[0][2 * p],     a[0], b[p][0], b[p][2]);
            mma_e4m3(acc[1][2 * p],     a[1], b[p][0], b[p][2]);
            mma_e4m3(acc[0][2 * p + 1], a[0], b[p][1], b[p][3]);
            mma_e4m3(acc[1][2 * p + 1], a[1], b[p][1], b[p][3]);
        }
    }
    __syncthreads();

    // ---- epilogue: masked exp-sum / pos-sum / pos-count (S = acc / 256) ----
    const float sc = 1.0f / 256.0f;
#pragma unroll
    for (int mt = 0; mt < 2; ++mt) {
#pragma unroll
        for (int h = 0; h < 2; ++h) {
            int r = mt * 2 + h;
            int rl = warp_m * 32 + mt * 16 + h * 8 + g;
            unsigned pw = (pmw >> (8 * r)) & 0xffu;
            unsigned nw = (nmw >> (8 * r)) & 0xffu;
            float dsum = 0.f, psum = 0.f;
            int np = __popc(pw);
#pragma unroll
            for (int nt = 0; nt < 4; ++nt) {
#pragma unroll
                for (int q = 0; q < 2; ++q) {
                    int k = nt * 2 + q;
                    float s = acc[mt][nt][h * 2 + q] * sc;
                    if ((pw >> k) & 1) psum += s;
                    else if ((nw >> k) & 1) dsum += __expf(s);
                }
            }
#pragma unroll
            for (int o = 1; o <= 2; o <<= 1) {
                dsum += __shfl_xor_sync(0xffffffffu, dsum, o);
                psum += __shfl_xor_sync(0xffffffffu, psum, o);
                np   += __shfl_xor_sync(0xffffffffu, np, o);
            }
            if (tig == 0) {
                atomicAdd(&sdn[rl], dsum);
                atomicAdd(&sps[rl], psum);
                atomicAdd(&sns[rl], np);
            }
        }
    }
    __syncthreads();
    if (tid < 128) {
        int grow = rbase + tid;
        if (grow < B) {
            atomicAdd(&g_denom[grow], sdn[tid]);
            atomicAdd(&g_pos[grow], sps[tid]);
            atomicAdd(&g_npos[grow], sns[tid]);
        }
    }
}

// ---------------------------------------------------------------------------
__global__ void finalize_kernel(float* __restrict__ out, int B) {
    __shared__ float red[256];
    int t = threadIdx.x;
    float v = 0.f;
    for (int r = t; r < B; r += 256)
        v += logf(g_denom[r]) - g_pos[r] / (float)g_npos[r];
    red[t] = v;
    __syncthreads();
    for (int s = 128; s > 0; s >>= 1) {
        if (t < s) red[t] += red[t + s];
        __syncthreads();
    }
    if (t == 0) out[0] = red[0] / (float)B;
}

// ---------------------------------------------------------------------------
extern "C" void kernel_launch(void* const* d_in, const int* in_sizes, int n_in,
                              void* d_out, int out_size) {
    const float* vfeat = (const float*)d_in[0];
    const float* tfeat = (const float*)d_in[1];
    const int*   label = (const int*)d_in[2];
    const int*   ids   = (const int*)d_in[3];
    (void)n_in; (void)out_size;

    double s0 = (double)in_sizes[0], s1 = (double)in_sizes[1], s2 = (double)in_sizes[2];
    int D = (int)(sqrt(s0 * s1 / s2) + 0.5);
    if (D <= 0) D = D_FIX;
    int B  = in_sizes[0] / D;
    int C  = in_sizes[1] / D;
    int NL = in_sizes[3];
    float* out = (float*)d_out;

    int ctiles = (NL + 63) / 64;            // 64-wide compact column tiles
    int padRows = ctiles * 64 - NL;
    int padBytes = padRows * D_FIX;
    size_t padOff = (size_t)NL * D_FIX;

    if (padBytes > 0)
        zero_pad_kernel<<<(padBytes + 255) / 256, 256>>>(padBytes, padOff);

    norm_fp8_kernel<<<(B + 7) / 8, 256>>>(vfeat, ids, B, 0.0f, 0, 0);
    norm_fp8_kernel<<<(NL + 7) / 8, 256>>>(tfeat, ids, NL, 1e-6f, 1, 1);

    size_t smem_bytes = (size_t)(128 + 64) * TS;   // 52224
    cudaFuncSetAttribute(gemm_loss8,
                         cudaFuncAttributeMaxDynamicSharedMemorySize,
                         (int)smem_bytes);
    dim3 grid(ctiles, (B + 127) / 128);
    gemm_loss8<<<grid, 256, smem_bytes>>>(label, ids, B, C, NL);

    finalize_kernel<<<1, 256>>>(out, B);
}

// round 14
// speedup vs baseline: 1.1106x; 1.1106x over previous
#include <cuda_runtime.h>
#include <cuda_bf16.h>
#include <math.h>
#include <cstdint>

#define D_FIX 256
#define C_MAX 50176
#define B_MAX 512
#define TS 272          // smem tile row stride in bytes (256 data + 16 pad)

// ---- device scratch (allocation-free: __device__ globals) ----
__device__ unsigned char g_tn8[(size_t)C_MAX * D_FIX];   // fp8 text (compact, x16)
__device__ unsigned char g_vn8[(size_t)B_MAX * D_FIX];   // fp8 visual (x16)
__device__ float g_denom[B_MAX];
__device__ float g_pos[B_MAX];
__device__ int   g_npos[B_MAX];
__device__ unsigned g_ctr;                               // CTA completion counter

// ---------------------------------------------------------------------------
__device__ __forceinline__ unsigned smemu32(const void* p) {
    return (unsigned)__cvta_generic_to_shared(p);
}
#define CP_ASYNC16(dst, src) \
    asm volatile("cp.async.cg.shared.global [%0], [%1], 16;\n" :: "r"(dst), "l"(src))
#define CP_COMMIT()  asm volatile("cp.async.commit_group;\n")
#define CP_WAIT0()   asm volatile("cp.async.wait_group 0;\n" ::: "memory")

// pack 4 floats -> 4 e4m3 bytes (byte0 = a); cvt.e4m3x2 writes a b16 dest
__device__ __forceinline__ unsigned pack_e4m3x4(float a, float b, float c, float d) {
    unsigned short lo, hi;
    asm("cvt.rn.satfinite.e4m3x2.f32 %0, %1, %2;" : "=h"(lo) : "f"(b), "f"(a));
    asm("cvt.rn.satfinite.e4m3x2.f32 %0, %1, %2;" : "=h"(hi) : "f"(d), "f"(c));
    return ((unsigned)hi << 16) | (unsigned)lo;
}

__device__ __forceinline__ void mma_e4m3(float c[4], const unsigned a[4],
                                         unsigned b0, unsigned b1) {
    asm volatile(
        "mma.sync.aligned.m16n8k32.row.col.f32.e4m3.e4m3.f32 "
        "{%0,%1,%2,%3}, {%4,%5,%6,%7}, {%8,%9}, {%0,%1,%2,%3};\n"
        : "+f"(c[0]), "+f"(c[1]), "+f"(c[2]), "+f"(c[3])
        : "r"(a[0]), "r"(a[1]), "r"(a[2]), "r"(a[3]), "r"(b0), "r"(b1));
}

// ---------------------------------------------------------------------------
// pad-zero only (launched only when NL % 64 != 0)
__global__ void zero_pad_kernel(int padBytes, size_t padOff) {
    int i = blockIdx.x * blockDim.x + threadIdx.x;
    if (i < padBytes) g_tn8[padOff + i] = 0;
}

// warp-per-row normalize -> fp8 (x16). gather=1: row i reads x[ids[i]].
// gather==0 (visual) also zeroes the per-row stats and the completion counter.
__global__ void norm_fp8_kernel(const float* __restrict__ x,
                                const int* __restrict__ ids,
                                int rows, float eps, int gather, int isText) {
    int i = blockIdx.x * 8 + (threadIdx.x >> 5);
    if (i >= rows) return;
    int lane = threadIdx.x & 31;
    if (!gather && lane == 0) {
        g_denom[i] = 0.f; g_pos[i] = 0.f; g_npos[i] = 0;
        if (i == 0) g_ctr = 0u;
    }
    int srcRow = gather ? ids[i] : i;
    const float4* xr = (const float4*)(x + (size_t)srcRow * D_FIX);
    float4 t0 = xr[lane], t1 = xr[lane + 32];
    float ss = t0.x * t0.x + t0.y * t0.y + t0.z * t0.z + t0.w * t0.w
             + t1.x * t1.x + t1.y * t1.y + t1.z * t1.z + t1.w * t1.w;
#pragma unroll
    for (int o = 16; o > 0; o >>= 1) ss += __shfl_xor_sync(0xffffffffu, ss, o);
    float inv = 16.0f / (eps + sqrtf(ss));
    unsigned w0 = pack_e4m3x4(t0.x * inv, t0.y * inv, t0.z * inv, t0.w * inv);
    unsigned w1 = pack_e4m3x4(t1.x * inv, t1.y * inv, t1.z * inv, t1.w * inv);
    unsigned* dst = (unsigned*)(isText ? g_tn8 : g_vn8) + (size_t)i * 64;
    dst[lane]      = w0;
    dst[lane + 32] = w1;
}

// ---------------------------------------------------------------------------
// fp8 GEMM tile 128(M)x64(N), warp tile 32x32, full K=256 resident,
// 3 CTAs/SM, fused label gather (one MLP-32 batch) + loss epilogue +
// last-CTA in-kernel finalize.
__global__ __launch_bounds__(256, 3)
void gemm_loss8(const int* __restrict__ label, const int* __restrict__ ids,
                float* __restrict__ out, int B, int C, int NL, int nCTAs) {
    extern __shared__ unsigned char dynraw[];
    __shared__ float sdn[128], sps[128];
    __shared__ int sns[128];
    __shared__ unsigned s_last;

    const int tid = threadIdx.x;
    const int cbase = blockIdx.x * 64;       // compact column base
    const int rbase = blockIdx.y * 128;

    const unsigned aB = smemu32(dynraw);
    const unsigned bB = aB + 128u * TS;

    // async tile loads: A 128 rows (8 chunks/thread), B 64 rows (4 chunks/thread)
#pragma unroll
    for (int m = 0; m < 8; ++m) {
        int id = m * 256 + tid;
        int r = id >> 4, cb = id & 15;
        CP_ASYNC16(aB + (unsigned)(r * TS + cb * 16),
                   g_vn8 + (size_t)(rbase + r) * D_FIX + cb * 16);
    }
#pragma unroll
    for (int m = 0; m < 4; ++m) {
        int id = m * 256 + tid;
        int r = id >> 4, cb = id & 15;
        CP_ASYNC16(bB + (unsigned)(r * TS + cb * 16),
                   g_tn8 + (size_t)(cbase + r) * D_FIX + cb * 16);
    }
    CP_COMMIT();

    if (tid < 128) { sdn[tid] = 0.f; sps[tid] = 0.f; sns[tid] = 0; }

    const int lane = tid & 31, wid = tid >> 5;
    const int g = lane >> 2, tig = lane & 3;
    const int warp_m = wid & 3, warp_n = wid >> 2;   // 4 x 2
    const int grp = lane >> 3, rin = lane & 7;

    // ---- fused label gather: 8 cols x 4 rows, ONE batch of 32 loads ----
    int idv[8]; unsigned vbits = 0;
#pragma unroll
    for (int k = 0; k < 8; ++k) {
        int cl = warp_n * 32 + (k >> 1) * 8 + 2 * tig + (k & 1);
        int gc = cbase + cl;
        bool v = (gc < NL);
        if (v) vbits |= 1u << k;
        idv[k] = ids[v ? gc : (NL - 1)];
    }
    int labs[4][8];
#pragma unroll
    for (int r = 0; r < 4; ++r) {
        int rl = warp_m * 32 + (r >> 1) * 16 + (r & 1) * 8 + g;
        const int* lrow = label + (size_t)(rbase + rl) * C;
#pragma unroll
        for (int k = 0; k < 8; ++k) labs[r][k] = __ldg(&lrow[idv[k]]);
    }
    unsigned pmw = 0, nmw = 0;    // packed: row-group r occupies bits [8r, 8r+8)
#pragma unroll
    for (int r = 0; r < 4; ++r) {
#pragma unroll
        for (int k = 0; k < 8; ++k) {
            if ((vbits >> k) & 1) {
                if (labs[r][k] != 0) pmw |= 1u << (8 * r + k);
                else                 nmw |= 1u << (8 * r + k);
            }
        }
    }

    float acc[2][4][4];
#pragma unroll
    for (int i = 0; i < 2; i++)
#pragma unroll
        for (int j = 0; j < 4; j++)
#pragma unroll
            for (int k = 0; k < 4; k++) acc[i][j][k] = 0.f;

    CP_WAIT0();
    __syncthreads();

    unsigned aBase[2], bBase[2];
#pragma unroll
    for (int mt = 0; mt < 2; ++mt) {
        int rowA = warp_m * 32 + mt * 16 + (grp & 1) * 8 + rin;
        aBase[mt] = aB + (unsigned)(rowA * TS + (grp >> 1) * 16);
    }
#pragma unroll
    for (int p = 0; p < 2; ++p) {
        int rowB = warp_n * 32 + p * 16 + ((grp & 2) ? 8 : 0) + rin;
        bBase[p] = bB + (unsigned)(rowB * TS + (grp & 1) * 16);
    }

#pragma unroll
    for (int ks = 0; ks < 8; ++ks) {          // K = 8 x 32 fp8
        const unsigned kof = ks * 32;
        unsigned a[2][4], b[2][4];
#pragma unroll
        for (int mt = 0; mt < 2; ++mt)
            asm volatile(
                "ldmatrix.sync.aligned.m8n8.x4.shared.b16 {%0,%1,%2,%3}, [%4];\n"
                : "=r"(a[mt][0]), "=r"(a[mt][1]), "=r"(a[mt][2]), "=r"(a[mt][3])
                : "r"(aBase[mt] + kof));
#pragma unroll
        for (int p = 0; p < 2; ++p)
            asm volatile(
                "ldmatrix.sync.aligned.m8n8.x4.shared.b16 {%0,%1,%2,%3}, [%4];\n"
                : "=r"(b[p][0]), "=r"(b[p][1]), "=r"(b[p][2]), "=r"(b[p][3])
                : "r"(bBase[p] + kof));
#pragma unroll
        for (int p = 0; p < 2; ++p) {
            mma_e4m3(acc[0][2 * p],     a[0], b[p][0], b[p][2]);
            mma_e4m3(acc[1][2 * p],     a[1], b[p][0], b[p][2]);
            mma_e4m3(acc[0][2 * p + 1], a[0], b[p][1], b[p][3]);
            mma_e4m3(acc[1][2 * p + 1], a[1], b[p][1], b[p][3]);
        }
    }
    __syncthreads();

    // ---- epilogue: masked exp-sum / pos-sum / pos-count (S = acc / 256) ----
    const float sc = 1.0f / 256.0f;
#pragma unroll
    for (int mt = 0; mt < 2; ++mt) {
#pragma unroll
        for (int h = 0; h < 2; ++h) {
            int r = mt * 2 + h;
            int rl = warp_m * 32 + mt * 16 + h * 8 + g;
            unsigned pw = (pmw >> (8 * r)) & 0xffu;
            unsigned nw = (nmw >> (8 * r)) & 0xffu;
            float dsum = 0.f, psum = 0.f;
            int np = __popc(pw);
#pragma unroll
            for (int nt = 0; nt < 4; ++nt) {
#pragma unroll
                for (int q = 0; q < 2; ++q) {
                    int k = nt * 2 + q;
                    float s = acc[mt][nt][h * 2 + q] * sc;
                    if ((pw >> k) & 1) psum += s;
                    else if ((nw >> k) & 1) dsum += __expf(s);
                }
            }
#pragma unroll
            for (int o = 1; o <= 2; o <<= 1) {
                dsum += __shfl_xor_sync(0xffffffffu, dsum, o);
                psum += __shfl_xor_sync(0xffffffffu, psum, o);
                np   += __shfl_xor_sync(0xffffffffu, np, o);
            }
            if (tig == 0) {
                atomicAdd(&sdn[rl], dsum);
                atomicAdd(&sps[rl], psum);
                atomicAdd(&sns[rl], np);
            }
        }
    }
    __syncthreads();
    if (tid < 128) {
        int grow = rbase + tid;
        if (grow < B) {
            atomicAdd(&g_denom[grow], sdn[tid]);
            atomicAdd(&g_pos[grow], sps[tid]);
            atomicAdd(&g_npos[grow], sns[tid]);
        }
    }

    // ---- last CTA finalizes ----
    __threadfence();
    __syncthreads();
    if (tid == 0) {
        unsigned done = atomicAdd(&g_ctr, 1u);
        s_last = (done == (unsigned)(nCTAs - 1)) ? 1u : 0u;
    }
    __syncthreads();
    if (s_last) {
        __shared__ float red[256];
        float v = 0.f;
        for (int r = tid; r < B; r += 256)
            v += logf(g_denom[r]) - g_pos[r] / (float)g_npos[r];
        red[tid] = v;
        __syncthreads();
        for (int s = 128; s > 0; s >>= 1) {
            if (tid < s) red[tid] += red[tid + s];
            __syncthreads();
        }
        if (tid == 0) out[0] = red[0] / (float)B;
    }
}

// ---------------------------------------------------------------------------
extern "C" void kernel_launch(void* const* d_in, const int* in_sizes, int n_in,
                              void* d_out, int out_size) {
    const float* vfeat = (const float*)d_in[0];
    const float* tfeat = (const float*)d_in[1];
    const int*   label = (const int*)d_in[2];
    const int*   ids   = (const int*)d_in[3];
    (void)n_in; (void)out_size;

    double s0 = (double)in_sizes[0], s1 = (double)in_sizes[1], s2 = (double)in_sizes[2];
    int D = (int)(sqrt(s0 * s1 / s2) + 0.5);
    if (D <= 0) D = D_FIX;
    int B  = in_sizes[0] / D;
    int C  = in_sizes[1] / D;
    int NL = in_sizes[3];
    float* out = (float*)d_out;

    int ctiles = (NL + 63) / 64;            // 64-wide compact column tiles
    int padRows = ctiles * 64 - NL;
    int padBytes = padRows * D_FIX;
    size_t padOff = (size_t)NL * D_FIX;

    if (padBytes > 0)
        zero_pad_kernel<<<(padBytes + 255) / 256, 256>>>(padBytes, padOff);

    norm_fp8_kernel<<<(B + 7) / 8, 256>>>(vfeat, ids, B, 0.0f, 0, 0);
    norm_fp8_kernel<<<(NL + 7) / 8, 256>>>(tfeat, ids, NL, 1e-6f, 1, 1);

    size_t smem_bytes = (size_t)(128 + 64) * TS;   // 52224
    cudaFuncSetAttribute(gemm_loss8,
                         cudaFuncAttributeMaxDynamicSharedMemorySize,
                         (int)smem_bytes);
    dim3 grid(ctiles, (B + 127) / 128);
    int nCTAs = ctiles * ((B + 127) / 128);
    gemm_loss8<<<grid, 256, smem_bytes>>>(label, ids, out, B, C, NL, nCTAs);
}

// round 15
// speedup vs baseline: 1.3170x; 1.1859x over previous
#include <cuda_runtime.h>
#include <cuda_bf16.h>
#include <math.h>
#include <cstdint>

#define D_FIX 256
#define C_MAX 50176
#define B_MAX 512
#define TS 272          // smem tile row stride in bytes (256 data + 16 pad)

// ---- device scratch (allocation-free: __device__ globals) ----
__device__ unsigned char g_tn8[(size_t)C_MAX * D_FIX];   // fp8 text (compact, x16)
__device__ unsigned char g_vn8[(size_t)B_MAX * D_FIX];   // fp8 visual (x16)
__device__ float g_denom[B_MAX];
__device__ float g_pos[B_MAX];
__device__ int   g_npos[B_MAX];

// ---------------------------------------------------------------------------
__device__ __forceinline__ unsigned smemu32(const void* p) {
    return (unsigned)__cvta_generic_to_shared(p);
}
#define CP_ASYNC16(dst, src) \
    asm volatile("cp.async.cg.shared.global [%0], [%1], 16;\n" :: "r"(dst), "l"(src))
#define CP_COMMIT()  asm volatile("cp.async.commit_group;\n")
#define CP_WAIT0()   asm volatile("cp.async.wait_group 0;\n" ::: "memory")

// pack 4 floats -> 4 e4m3 bytes (byte0 = a); cvt.e4m3x2 writes a b16 dest
__device__ __forceinline__ unsigned pack_e4m3x4(float a, float b, float c, float d) {
    unsigned short lo, hi;
    asm("cvt.rn.satfinite.e4m3x2.f32 %0, %1, %2;" : "=h"(lo) : "f"(b), "f"(a));
    asm("cvt.rn.satfinite.e4m3x2.f32 %0, %1, %2;" : "=h"(hi) : "f"(d), "f"(c));
    return ((unsigned)hi << 16) | (unsigned)lo;
}

__device__ __forceinline__ void mma_e4m3(float c[4], const unsigned a[4],
                                         unsigned b0, unsigned b1) {
    asm volatile(
        "mma.sync.aligned.m16n8k32.row.col.f32.e4m3.e4m3.f32 "
        "{%0,%1,%2,%3}, {%4,%5,%6,%7}, {%8,%9}, {%0,%1,%2,%3};\n"
        : "+f"(c[0]), "+f"(c[1]), "+f"(c[2]), "+f"(c[3])
        : "r"(a[0]), "r"(a[1]), "r"(a[2]), "r"(a[3]), "r"(b0), "r"(b1));
}

// ---------------------------------------------------------------------------
// pad-zero only (launched only when NL % 64 != 0)
__global__ void zero_pad_kernel(int padBytes, size_t padOff) {
    int i = blockIdx.x * blockDim.x + threadIdx.x;
    if (i < padBytes) g_tn8[padOff + i] = 0;
}

// ONE fused normalize kernel: warp-per-row.
// rows [0, B)        : visual, no gather, eps=0, also zero per-row stats
// rows [B, B+NL)     : text, gather via ids, eps=1e-6
__global__ void norm_fp8_fused(const float* __restrict__ vfeat,
                               const float* __restrict__ tfeat,
                               const int* __restrict__ ids,
                               int B, int NL) {
    int i = blockIdx.x * 8 + (threadIdx.x >> 5);
    if (i >= B + NL) return;
    int lane = threadIdx.x & 31;
    const float* src;
    unsigned* dst;
    float eps;
    if (i < B) {
        if (lane == 0) { g_denom[i] = 0.f; g_pos[i] = 0.f; g_npos[i] = 0; }
        src = vfeat + (size_t)i * D_FIX;
        dst = (unsigned*)g_vn8 + (size_t)i * 64;
        eps = 0.0f;
    } else {
        int j = i - B;
        src = tfeat + (size_t)ids[j] * D_FIX;
        dst = (unsigned*)g_tn8 + (size_t)j * 64;
        eps = 1e-6f;
    }
    const float4* xr = (const float4*)src;
    float4 t0 = xr[lane], t1 = xr[lane + 32];
    float ss = t0.x * t0.x + t0.y * t0.y + t0.z * t0.z + t0.w * t0.w
             + t1.x * t1.x + t1.y * t1.y + t1.z * t1.z + t1.w * t1.w;
#pragma unroll
    for (int o = 16; o > 0; o >>= 1) ss += __shfl_xor_sync(0xffffffffu, ss, o);
    float inv = 16.0f / (eps + sqrtf(ss));
    unsigned w0 = pack_e4m3x4(t0.x * inv, t0.y * inv, t0.z * inv, t0.w * inv);
    unsigned w1 = pack_e4m3x4(t1.x * inv, t1.y * inv, t1.z * inv, t1.w * inv);
    dst[lane]      = w0;
    dst[lane + 32] = w1;
}

// ---------------------------------------------------------------------------
// fp8 GEMM tile 128(M)x64(N), warp tile 32x32, full K=256 resident,
// 3 CTAs/SM, fused label gather (single MLP-32 batch) + loss epilogue.
// (byte-exact R12 configuration — measured 66.5 us, regs 80)
__global__ __launch_bounds__(256, 3)
void gemm_loss8(const int* __restrict__ label, const int* __restrict__ ids,
                int B, int C, int NL) {
    extern __shared__ unsigned char dynraw[];
    __shared__ float sdn[128], sps[128];
    __shared__ int sns[128];

    const int tid = threadIdx.x;
    const int cbase = blockIdx.x * 64;       // compact column base
    const int rbase = blockIdx.y * 128;

    unsigned base = (smemu32(dynraw) + 1023u) & ~1023u;
    const unsigned aB = base;
    const unsigned bB = base + 128u * TS;

    // async tile loads: A 128 rows (8 chunks/thread), B 64 rows (4 chunks/thread)
#pragma unroll
    for (int m = 0; m < 8; ++m) {
        int id = m * 256 + tid;
        int r = id >> 4, cb = id & 15;
        CP_ASYNC16(aB + (unsigned)(r * TS + cb * 16),
                   g_vn8 + (size_t)(rbase + r) * D_FIX + cb * 16);
    }
#pragma unroll
    for (int m = 0; m < 4; ++m) {
        int id = m * 256 + tid;
        int r = id >> 4, cb = id & 15;
        CP_ASYNC16(bB + (unsigned)(r * TS + cb * 16),
                   g_tn8 + (size_t)(cbase + r) * D_FIX + cb * 16);
    }
    CP_COMMIT();

    if (tid < 128) { sdn[tid] = 0.f; sps[tid] = 0.f; sns[tid] = 0; }

    const int lane = tid & 31, wid = tid >> 5;
    const int g = lane >> 2, tig = lane & 3;
    const int warp_m = wid & 3, warp_n = wid >> 2;   // 4 x 2
    const int grp = lane >> 3, rin = lane & 7;

    // ---- fused label gather: 8 cols x 4 rows, ONE batch of 32 loads ----
    int idv[8]; unsigned vbits = 0;
#pragma unroll
    for (int k = 0; k < 8; ++k) {
        int cl = warp_n * 32 + (k >> 1) * 8 + 2 * tig + (k & 1);
        int gc = cbase + cl;
        bool v = (gc < NL);
        if (v) vbits |= 1u << k;
        idv[k] = ids[v ? gc : (NL - 1)];
    }
    int labs[4][8];
#pragma unroll
    for (int r = 0; r < 4; ++r) {
        int rl = warp_m * 32 + (r >> 1) * 16 + (r & 1) * 8 + g;
        const int* lrow = label + (size_t)(rbase + rl) * C;
#pragma unroll
        for (int k = 0; k < 8; ++k) labs[r][k] = __ldg(&lrow[idv[k]]);
    }
    unsigned pm[4], nm[4];
#pragma unroll
    for (int r = 0; r < 4; ++r) {
        unsigned p = 0, n = 0;
#pragma unroll
        for (int k = 0; k < 8; ++k) {
            if ((vbits >> k) & 1) {
                if (labs[r][k] != 0) p |= 1u << k;
                else                 n |= 1u << k;
            }
        }
        pm[r] = p; nm[r] = n;
    }

    float acc[2][4][4];
#pragma unroll
    for (int i = 0; i < 2; i++)
#pragma unroll
        for (int j = 0; j < 4; j++)
#pragma unroll
            for (int k = 0; k < 4; k++) acc[i][j][k] = 0.f;

    CP_WAIT0();
    __syncthreads();

    unsigned aBase[2], bBase[2];
#pragma unroll
    for (int mt = 0; mt < 2; ++mt) {
        int rowA = warp_m * 32 + mt * 16 + (grp & 1) * 8 + rin;
        aBase[mt] = aB + (unsigned)(rowA * TS + (grp >> 1) * 16);
    }
#pragma unroll
    for (int p = 0; p < 2; ++p) {
        int rowB = warp_n * 32 + p * 16 + ((grp & 2) ? 8 : 0) + rin;
        bBase[p] = bB + (unsigned)(rowB * TS + (grp & 1) * 16);
    }

#pragma unroll
    for (int ks = 0; ks < 8; ++ks) {          // K = 8 x 32 fp8
        const unsigned kof = ks * 32;
        unsigned a[2][4], b[2][4];
#pragma unroll
        for (int mt = 0; mt < 2; ++mt)
            asm volatile(
                "ldmatrix.sync.aligned.m8n8.x4.shared.b16 {%0,%1,%2,%3}, [%4];\n"
                : "=r"(a[mt][0]), "=r"(a[mt][1]), "=r"(a[mt][2]), "=r"(a[mt][3])
                : "r"(aBase[mt] + kof));
#pragma unroll
        for (int p = 0; p < 2; ++p)
            asm volatile(
                "ldmatrix.sync.aligned.m8n8.x4.shared.b16 {%0,%1,%2,%3}, [%4];\n"
                : "=r"(b[p][0]), "=r"(b[p][1]), "=r"(b[p][2]), "=r"(b[p][3])
                : "r"(bBase[p] + kof));
#pragma unroll
        for (int p = 0; p < 2; ++p) {
            mma_e4m3(acc[0][2 * p],     a[0], b[p][0], b[p][2]);
            mma_e4m3(acc[1][2 * p],     a[1], b[p][0], b[p][2]);
            mma_e4m3(acc[0][2 * p + 1], a[0], b[p][1], b[p][3]);
            mma_e4m3(acc[1][2 * p + 1], a[1], b[p][1], b[p][3]);
        }
    }
    __syncthreads();

    // ---- epilogue: masked exp-sum / pos-sum / pos-count (S = acc / 256) ----
    const float sc = 1.0f / 256.0f;
#pragma unroll
    for (int mt = 0; mt < 2; ++mt) {
#pragma unroll
        for (int h = 0; h < 2; ++h) {
            int r = mt * 2 + h;
            int rl = warp_m * 32 + mt * 16 + h * 8 + g;
            unsigned pw = pm[r], nw = nm[r];
            float dsum = 0.f, psum = 0.f; int np = 0;
#pragma unroll
            for (int nt = 0; nt < 4; ++nt) {
#pragma unroll
                for (int q = 0; q < 2; ++q) {
                    int k = nt * 2 + q;
                    float s = acc[mt][nt][h * 2 + q] * sc;
                    if ((pw >> k) & 1) { psum += s; np += 1; }
                    else if ((nw >> k) & 1) dsum += __expf(s);
                }
            }
#pragma unroll
            for (int o = 1; o <= 2; o <<= 1) {
                dsum += __shfl_xor_sync(0xffffffffu, dsum, o);
                psum += __shfl_xor_sync(0xffffffffu, psum, o);
                np   += __shfl_xor_sync(0xffffffffu, np, o);
            }
            if (tig == 0) {
                atomicAdd(&sdn[rl], dsum);
                atomicAdd(&sps[rl], psum);
                atomicAdd(&sns[rl], np);
            }
        }
    }
    __syncthreads();
    if (tid < 128) {
        int grow = rbase + tid;
        if (grow < B) {
            atomicAdd(&g_denom[grow], sdn[tid]);
            atomicAdd(&g_pos[grow], sps[tid]);
            atomicAdd(&g_npos[grow], sns[tid]);
        }
    }
}

// ---------------------------------------------------------------------------
__global__ void finalize_kernel(float* __restrict__ out, int B) {
    __shared__ float red[256];
    int t = threadIdx.x;
    float v = 0.f;
    for (int r = t; r < B; r += 256)
        v += __logf(g_denom[r]) - g_pos[r] / (float)g_npos[r];
    red[t] = v;
    __syncthreads();
    for (int s = 128; s > 0; s >>= 1) {
        if (t < s) red[t] += red[t + s];
        __syncthreads();
    }
    if (t == 0) out[0] = red[0] / (float)B;
}

// ---------------------------------------------------------------------------
extern "C" void kernel_launch(void* const* d_in, const int* in_sizes, int n_in,
                              void* d_out, int out_size) {
    const float* vfeat = (const float*)d_in[0];
    const float* tfeat = (const float*)d_in[1];
    const int*   label = (const int*)d_in[2];
    const int*   ids   = (const int*)d_in[3];
    (void)n_in; (void)out_size;

    double s0 = (double)in_sizes[0], s1 = (double)in_sizes[1], s2 = (double)in_sizes[2];
    int D = (int)(sqrt(s0 * s1 / s2) + 0.5);
    if (D <= 0) D = D_FIX;
    int B  = in_sizes[0] / D;
    int C  = in_sizes[1] / D;
    int NL = in_sizes[3];
    float* out = (float*)d_out;

    int ctiles = (NL + 63) / 64;            // 64-wide compact column tiles
    int padRows = ctiles * 64 - NL;
    int padBytes = padRows * D_FIX;
    size_t padOff = (size_t)NL * D_FIX;

    if (padBytes > 0)
        zero_pad_kernel<<<(padBytes + 255) / 256, 256>>>(padBytes, padOff);

    norm_fp8_fused<<<(B + NL + 7) / 8, 256>>>(vfeat, tfeat, ids, B, NL);

    size_t smem_bytes = 1024 + (size_t)(128 + 64) * TS;   // R12 layout
    cudaFuncSetAttribute(gemm_loss8,
                         cudaFuncAttributeMaxDynamicSharedMemorySize,
                         (int)smem_bytes);
    dim3 grid(ctiles, (B + 127) / 128);
    gemm_loss8<<<grid, 256, smem_bytes>>>(label, ids, B, C, NL);

    finalize_kernel<<<1, 256>>>(out, B);
}